// round 1
// baseline (speedup 1.0000x reference)
#include <cuda_runtime.h>
#include <cuda_bf16.h>

// SuperLinear: out[b,n] = sum_m x[b,n,m] * w1[m,0,n] + b1[0,n,0]
// B=256, N=4096, M=64, H=1. Pure HBM-streaming kernel.
//
// Layouts (row-major, fp32):
//   x  : [B, N, M]   -> x[((b*N)+n)*M + m]   (per-(b,n) row of 64 floats, contiguous)
//   w1 : [M, 1, N]   -> w1[m*N + n]          (lane-coalesced in n)
//   b1 : [1, N, 1]   -> b1[n]
//   out: [B, N]      -> out[b*N + n]

#define SL_B 256
#define SL_N 4096
#define SL_M 64
#define TILE_N 128   // threads per block, each owns one n
#define TILE_B 4     // b-values per thread (w-register reuse + ILP)

__global__ __launch_bounds__(TILE_N)
void superlinear_kernel(const float* __restrict__ x,
                        const float* __restrict__ w1,
                        const float* __restrict__ b1,
                        float* __restrict__ out)
{
    const int n  = blockIdx.x * TILE_N + threadIdx.x;   // 0..4095
    const int b0 = blockIdx.y * TILE_B;                 // 0..255 step 4

    // Hoist this n's weight column into registers (reused across TILE_B b's).
    // Coalesced: lanes have consecutive n -> 128B/warp per m. L2-resident after
    // the first b-tile touches it (w1 is only 1 MB total).
    float wreg[SL_M];
#pragma unroll
    for (int m = 0; m < SL_M; ++m) {
        wreg[m] = __ldg(&w1[(size_t)m * SL_N + n]);
    }
    const float bias = __ldg(&b1[n]);

#pragma unroll
    for (int bb = 0; bb < TILE_B; ++bb) {
        const int b = b0 + bb;
        const float4* xr =
            reinterpret_cast<const float4*>(x + ((size_t)b * SL_N + n) * SL_M);
        float acc0 = bias, acc1 = 0.f, acc2 = 0.f, acc3 = 0.f;
#pragma unroll
        for (int m4 = 0; m4 < SL_M / 4; m4 += 4) {
            float4 v0 = __ldg(&xr[m4 + 0]);
            float4 v1 = __ldg(&xr[m4 + 1]);
            float4 v2 = __ldg(&xr[m4 + 2]);
            float4 v3 = __ldg(&xr[m4 + 3]);
            acc0 += v0.x * wreg[4 * m4 + 0]  + v0.y * wreg[4 * m4 + 1]
                  + v0.z * wreg[4 * m4 + 2]  + v0.w * wreg[4 * m4 + 3];
            acc1 += v1.x * wreg[4 * m4 + 4]  + v1.y * wreg[4 * m4 + 5]
                  + v1.z * wreg[4 * m4 + 6]  + v1.w * wreg[4 * m4 + 7];
            acc2 += v2.x * wreg[4 * m4 + 8]  + v2.y * wreg[4 * m4 + 9]
                  + v2.z * wreg[4 * m4 + 10] + v2.w * wreg[4 * m4 + 11];
            acc3 += v3.x * wreg[4 * m4 + 12] + v3.y * wreg[4 * m4 + 13]
                  + v3.z * wreg[4 * m4 + 14] + v3.w * wreg[4 * m4 + 15];
        }
        out[(size_t)b * SL_N + n] = (acc0 + acc1) + (acc2 + acc3);
    }
}

extern "C" void kernel_launch(void* const* d_in, const int* in_sizes, int n_in,
                              void* d_out, int out_size)
{
    const float* x  = (const float*)d_in[0];   // [256, 4096, 64]
    const float* w1 = (const float*)d_in[1];   // [64, 1, 4096]
    const float* b1 = (const float*)d_in[2];   // [1, 4096, 1]
    float* out = (float*)d_out;                // [256, 4096]

    dim3 grid(SL_N / TILE_N, SL_B / TILE_B);   // (32, 64) = 2048 blocks
    superlinear_kernel<<<grid, TILE_N>>>(x, w1, b1, out);
}

// round 3
// speedup vs baseline: 1.2225x; 1.2225x over previous
#include <cuda_runtime.h>
#include <cuda_bf16.h>

// SuperLinear: out[b,n] = sum_m x[b,n,m] * w1[m,0,n] + b1[0,n,0]
// B=256, N=4096, M=64, H=1. HBM-bound; R1 showed L1-wavefront bottleneck
// (strided per-thread row reads, 32 wavefronts/warp-LDG). Fix: stage x tiles
// through smem with coalesced cp.async.cg (L1 bypass), compute from
// conflict-free padded smem.
//
// Layouts (fp32, row-major):
//   x  : [B, N, M]  x[((b*N)+n)*M + m]
//   w1 : [M, 1, N]  w1[m*N + n]
//   b1 : [1, N, 1]  b1[n]
//   out: [B, N]     out[b*N + n]

#define SL_B 256
#define SL_N 4096
#define SL_M 64
#define BLK_N 128     // n-tile = threads per block
#define TILE_B 4      // b iterations per block
#define ROW_STRIDE 68 // smem row stride in floats: 68 mod 32 == 4 -> conflict-free LDS.128

__global__ __launch_bounds__(BLK_N, 6)
void superlinear_kernel(const float* __restrict__ x,
                        const float* __restrict__ w1,
                        const float* __restrict__ b1,
                        float* __restrict__ out)
{
    __shared__ float xs[BLK_N * ROW_STRIDE];   // 34,816 B -> 6 blocks/SM

    const int tid = threadIdx.x;
    const int n   = blockIdx.x * BLK_N + tid;
    const int b0  = blockIdx.y * TILE_B;

    // Per-thread weight column (reused across TILE_B b's). Coalesced in n;
    // w1 is 1 MB total -> L2-resident after first wave.
    float wreg[SL_M];
#pragma unroll
    for (int m = 0; m < SL_M; ++m)
        wreg[m] = __ldg(&w1[(size_t)m * SL_N + n]);
    const float bias = __ldg(&b1[n]);

    // Byte base of this block's x tile at b = b0.
    const char* gbase = reinterpret_cast<const char*>(
        x + ((size_t)b0 * SL_N + (size_t)blockIdx.x * BLK_N) * SL_M);

    for (int bb = 0; bb < TILE_B; ++bb) {
        // ---- Stage x[b, n0:n0+128, 0:64] (32 KB contiguous) into smem ----
        // 2048 16B chunks; 16 per thread; perfectly coalesced; L1-bypass (.cg).
        const char* g = gbase + (size_t)bb * (SL_N * SL_M * 4);
#pragma unroll
        for (int i = 0; i < 16; ++i) {
            const int k   = i * BLK_N + tid;      // 0..2047 (16B chunk index)
            const int row = k >> 4;               // 0..127
            const int col = k & 15;               // 0..15
            unsigned saddr = (unsigned)__cvta_generic_to_shared(
                &xs[row * ROW_STRIDE + col * 4]);
            asm volatile("cp.async.cg.shared.global [%0], [%1], 16;\n"
                         :: "r"(saddr), "l"(g + (size_t)k * 16) : "memory");
        }
        asm volatile("cp.async.commit_group;\n" ::: "memory");
        asm volatile("cp.async.wait_group 0;\n" ::: "memory");
        __syncthreads();

        // ---- Dot product from smem (row = tid, conflict-free) ----
        const float4* xrow = reinterpret_cast<const float4*>(&xs[tid * ROW_STRIDE]);
        float acc0 = 0.f, acc1 = 0.f, acc2 = 0.f, acc3 = 0.f;
#pragma unroll
        for (int i = 0; i < 16; i += 4) {
            float4 v0 = xrow[i + 0];
            float4 v1 = xrow[i + 1];
            float4 v2 = xrow[i + 2];
            float4 v3 = xrow[i + 3];
            acc0 += v0.x * wreg[4*i + 0]  + v0.y * wreg[4*i + 1]
                  + v0.z * wreg[4*i + 2]  + v0.w * wreg[4*i + 3];
            acc1 += v1.x * wreg[4*i + 4]  + v1.y * wreg[4*i + 5]
                  + v1.z * wreg[4*i + 6]  + v1.w * wreg[4*i + 7];
            acc2 += v2.x * wreg[4*i + 8]  + v2.y * wreg[4*i + 9]
                  + v2.z * wreg[4*i + 10] + v2.w * wreg[4*i + 11];
            acc3 += v3.x * wreg[4*i + 12] + v3.y * wreg[4*i + 13]
                  + v3.z * wreg[4*i + 14] + v3.w * wreg[4*i + 15];
        }
        out[(size_t)(b0 + bb) * SL_N + n] = (acc0 + acc1) + (acc2 + acc3) + bias;

        if (bb != TILE_B - 1)
            __syncthreads();   // protect xs before next stage overwrites it
    }
}

extern "C" void kernel_launch(void* const* d_in, const int* in_sizes, int n_in,
                              void* d_out, int out_size)
{
    const float* x  = (const float*)d_in[0];   // [256, 4096, 64]
    const float* w1 = (const float*)d_in[1];   // [64, 1, 4096]
    const float* b1 = (const float*)d_in[2];   // [1, 4096, 1]
    float* out = (float*)d_out;                // [256, 4096]

    dim3 grid(SL_N / BLK_N, SL_B / TILE_B);    // (32, 64) = 2048 blocks
    superlinear_kernel<<<grid, BLK_N>>>(x, w1, b1, out);
}